// round 13
// baseline (speedup 1.0000x reference)
#include <cuda_runtime.h>

#define N_MAX 50000
#define E_MAX 800000
#define HD 128
#define NH 8

// ---- scratch (device globals; no allocation allowed) ----
__device__ float g_hf[N_MAX * HD];      // nfeat @ W_fc
__device__ float g_el[N_MAX * NH];
__device__ float g_er[N_MAX * NH];
__device__ float g_Sagg[N_MAX * HD];    // segment_sum(efeat)  (atomic scatter)
__device__ float g_invm[N_MAX];         // 1/max(deg,1)
__device__ int   g_cnt[N_MAX];          // dst histogram
__device__ int   g_off[N_MAX + 1];      // CSR offsets (immutable)
__device__ int   g_cur[N_MAX];          // mutable cursor for permute
__device__ int   g_ps[E_MAX];           // src grouped by dst

// vectorized float4 reduction to global memory (sm_90+)
__device__ __forceinline__ void red_add_v4(float* p, float x, float y, float z, float w) {
    asm volatile("red.global.add.v4.f32 [%0], {%1,%2,%3,%4};"
                 :: "l"(p), "f"(x), "f"(y), "f"(z), "f"(w) : "memory");
}

// packed f32x2 helpers (FFMA2 — PTX-only path on sm_103a)
__device__ __forceinline__ unsigned long long pack2(float lo, float hi) {
    unsigned long long r;
    asm("mov.b64 %0, {%1, %2};" : "=l"(r) : "r"(__float_as_uint(lo)), "r"(__float_as_uint(hi)));
    return r;
}
__device__ __forceinline__ void fma2(unsigned long long& acc, unsigned long long a, unsigned long long b) {
    asm("fma.rn.f32x2 %0, %1, %2, %0;" : "+l"(acc) : "l"(a), "l"(b));
}
__device__ __forceinline__ void unpack2(unsigned long long v, float& lo, float& hi) {
    unsigned int l, h;
    asm("mov.b64 {%0, %1}, %2;" : "=r"(l), "=r"(h) : "l"(v));
    lo = __uint_as_float(l); hi = __uint_as_float(h);
}

__device__ __forceinline__ float leaky02(float x) { return x > 0.f ? x : 0.2f * x; }

// ---------------- GEMM: 128x128 block tile, 8x8 per thread ----------------
// mode 0: out = A@W, plus el/er head reductions.
// mode 1: fused finalize: out[row] += (A@W)[row] * g_invm[row]   (out preloaded)
#define KC 32
__global__ __launch_bounds__(256, 2)
void gemm_kernel(const float* __restrict__ A, const float* __restrict__ W,
                 float* __restrict__ out, int nrows, int mode,
                 const float* __restrict__ attn_l, const float* __restrict__ attn_r) {
    __shared__ float Ws[KC][128];
    __shared__ float As[128][KC + 4];
    int t = threadIdx.x;
    int tx = t & 15;
    int ty = t >> 4;
    int rbase = blockIdx.x * 128;

    unsigned long long acc[8][4];
#pragma unroll
    for (int i = 0; i < 8; i++)
#pragma unroll
        for (int j = 0; j < 4; j++) acc[i][j] = 0ull;

    for (int kc = 0; kc < 4; kc++) {
#pragma unroll
        for (int i = 0; i < 4; i++) {
            int lin = i * 256 + t;
            int r = lin >> 5, c4 = lin & 31;
            *((float4*)&Ws[r][c4 * 4]) = ((const float4*)W)[(kc * 32 + r) * 32 + c4];
        }
#pragma unroll
        for (int i = 0; i < 4; i++) {
            int lin = i * 256 + t;
            int r = lin >> 3, k4 = lin & 7;
            int row = rbase + r;
            float4 v = (row < nrows) ? ((const float4*)A)[(size_t)row * 32 + kc * 8 + k4]
                                     : make_float4(0.f, 0.f, 0.f, 0.f);
            *((float4*)&As[r][k4 * 4]) = v;
        }
        __syncthreads();
#pragma unroll
        for (int k = 0; k < KC; k++) {
            unsigned long long w2[4];
#pragma unroll
            for (int j = 0; j < 4; j++)
                w2[j] = *(const unsigned long long*)&Ws[k][tx * 8 + j * 2];
#pragma unroll
            for (int i = 0; i < 8; i++) {
                float a = As[ty * 8 + i][k];
                unsigned long long aa = pack2(a, a);
#pragma unroll
                for (int j = 0; j < 4; j++) fma2(acc[i][j], aa, w2[j]);
            }
        }
        __syncthreads();
    }

    float al[8], ar[8];
    if (mode == 0) {
#pragma unroll
        for (int j = 0; j < 8; j++) { al[j] = attn_l[tx * 8 + j]; ar[j] = attn_r[tx * 8 + j]; }
    }

#pragma unroll
    for (int i = 0; i < 8; i++) {
        int row = rbase + ty * 8 + i;
        float c[8];
#pragma unroll
        for (int j = 0; j < 4; j++) unpack2(acc[i][j], c[2 * j], c[2 * j + 1]);
        if (mode == 0) {
            if (row < nrows) {
                *(float4*)&out[(size_t)row * 128 + tx * 8]     = make_float4(c[0], c[1], c[2], c[3]);
                *(float4*)&out[(size_t)row * 128 + tx * 8 + 4] = make_float4(c[4], c[5], c[6], c[7]);
            }
            float pl = 0.f, pr = 0.f;
#pragma unroll
            for (int j = 0; j < 8; j++) { pl += c[j] * al[j]; pr += c[j] * ar[j]; }
            pl += __shfl_xor_sync(0xffffffffu, pl, 1);
            pr += __shfl_xor_sync(0xffffffffu, pr, 1);
            if ((tx & 1) == 0 && row < nrows) {
                g_el[row * NH + (tx >> 1)] = pl;
                g_er[row * NH + (tx >> 1)] = pr;
            }
        } else if (row < nrows) {
            float im = g_invm[row];
            float4 o0 = *(const float4*)&out[(size_t)row * 128 + tx * 8];
            float4 o1 = *(const float4*)&out[(size_t)row * 128 + tx * 8 + 4];
            o0.x += c[0] * im; o0.y += c[1] * im; o0.z += c[2] * im; o0.w += c[3] * im;
            o1.x += c[4] * im; o1.y += c[5] * im; o1.z += c[6] * im; o1.w += c[7] * im;
            *(float4*)&out[(size_t)row * 128 + tx * 8]     = o0;
            *(float4*)&out[(size_t)row * 128 + tx * 8 + 4] = o1;
        }
    }
}

// ---------------- scatter: Sagg[dst] += efeat[e]  (+ fused dst histogram) -----------
// Full chip, 4 edges per warp, loads batched for MLP. Only atomic traffic in flight.
__global__ __launch_bounds__(256)
void scatter_kernel(const float4* __restrict__ efeat4, const int* __restrict__ dst, int E) {
    int w = (blockIdx.x * blockDim.x + threadIdx.x) >> 5;
    int lane = threadIdx.x & 31;
    int e0 = w * 4;
    if (e0 >= E) return;
    int ne = E - e0; if (ne > 4) ne = 4;

    int d[4]; float4 v[4];
#pragma unroll
    for (int q = 0; q < 4; q++) d[q] = dst[e0 + (q < ne ? q : ne - 1)];
#pragma unroll
    for (int q = 0; q < 4; q++)
        v[q] = __ldcs(&efeat4[(size_t)(e0 + (q < ne ? q : ne - 1)) * 32 + lane]);

    if (lane == 0) {
#pragma unroll
        for (int q = 0; q < 4; q++)
            if (q < ne) atomicAdd(&g_cnt[d[q]], 1);
    }
#pragma unroll
    for (int q = 0; q < 4; q++)
        if (q < ne)
            red_add_v4(&g_Sagg[(size_t)d[q] * 128 + lane * 4],
                       v[q].x, v[q].y, v[q].z, v[q].w);
}

// ---------------- scan / permute ----------------
__global__ void scan_kernel(int N, int E) {   // single block, 1024 threads
    __shared__ int s[1024];
    int tid = threadIdx.x;
    int per = (N + 1023) >> 10;
    int beg = tid * per, fin = beg + per; if (fin > N) fin = N; if (beg > N) beg = N;
    int sum = 0;
#pragma unroll 4
    for (int i = beg; i < fin; i++) sum += g_cnt[i];
    s[tid] = sum;
    __syncthreads();
    for (int off = 1; off < 1024; off <<= 1) {
        int u = (tid >= off) ? s[tid - off] : 0;
        __syncthreads();
        s[tid] += u;
        __syncthreads();
    }
    int run = s[tid] - sum;                   // exclusive base for this chunk
    for (int i = beg; i < fin; i++) {
        int c = g_cnt[i];
        g_off[i] = run;
        g_cur[i] = run;
        run += c;
    }
    if (tid == 0) g_off[N] = E;
}

__global__ void permute_kernel(const int* __restrict__ src, const int* __restrict__ dst, int E) {
    int e = blockIdx.x * blockDim.x + threadIdx.x;
    if (e >= E) return;
    int d = __ldcs(&dst[e]);
    int pos = atomicAdd(&g_cur[d], 1);
    g_ps[pos] = __ldcs(&src[e]);
}

// ---------------- node aggregation: one warp per node, atomic-free, full chip -------
// out[n] = (Σ ex·hf[s])/denom + bias + hf[n]/(deg+1) + b_e·(deg>0);  invm[n] stored.
// Only hf/el L2 gathers here — efeat handled by scatter_kernel.
__global__ __launch_bounds__(256)
void node_agg_kernel(float* __restrict__ out,
                     const float4* __restrict__ bias4, const float4* __restrict__ be4, int N) {
    int n = (blockIdx.x * blockDim.x + threadIdx.x) >> 5;
    if (n >= N) return;
    int lane = threadIdx.x & 31;
    int h = lane >> 2;
    int start = g_off[n], end = g_off[n + 1];
    int deg = end - start;
    float er_n = g_er[n * NH + h];
    const float4* hf4 = (const float4*)g_hf;

    float4 aO = make_float4(0.f, 0.f, 0.f, 0.f);
    float dacc = 0.f;
    int p = start;
#pragma unroll 1
    for (; p + 4 <= end; p += 4) {
        int s[4]; float4 hv[4]; float x[4];
#pragma unroll
        for (int q = 0; q < 4; q++) s[q] = __ldg(&g_ps[p + q]);
#pragma unroll
        for (int q = 0; q < 4; q++) hv[q] = hf4[(size_t)s[q] * 32 + lane];
#pragma unroll
        for (int q = 0; q < 4; q++)
            x[q] = __expf(leaky02(__ldg(&g_el[s[q] * NH + h]) + er_n));
#pragma unroll
        for (int q = 0; q < 4; q++) {
            dacc += x[q];
            aO.x += x[q] * hv[q].x; aO.y += x[q] * hv[q].y;
            aO.z += x[q] * hv[q].z; aO.w += x[q] * hv[q].w;
        }
    }
    for (; p < end; p++) {
        int s0 = __ldg(&g_ps[p]);
        float4 h0 = hf4[(size_t)s0 * 32 + lane];
        float x0 = __expf(leaky02(__ldg(&g_el[s0 * NH + h]) + er_n));
        dacc += x0;
        aO.x += x0 * h0.x; aO.y += x0 * h0.y; aO.z += x0 * h0.z; aO.w += x0 * h0.w;
    }

    float invden = dacc > 0.f ? 1.f / dacc : 0.f;
    float deg_f = (float)deg;
    float inv1 = 1.f / (deg_f + 1.f);
    float gate = deg > 0 ? 1.f : 0.f;
    float4 hn = hf4[(size_t)n * 32 + lane];
    float4 b  = bias4[lane];
    float4 be = be4[lane];
    float4 o;
    o.x = aO.x * invden + b.x + hn.x * inv1 + be.x * gate;
    o.y = aO.y * invden + b.y + hn.y * inv1 + be.y * gate;
    o.z = aO.z * invden + b.z + hn.z * inv1 + be.z * gate;
    o.w = aO.w * invden + b.w + hn.w * inv1 + be.w * gate;
    ((float4*)out)[(size_t)n * 32 + lane] = o;
    if (lane == 0) g_invm[n] = 1.f / fmaxf(deg_f, 1.f);
}

extern "C" void kernel_launch(void* const* d_in, const int* in_sizes, int n_in,
                              void* d_out, int out_size) {
    const float* nfeat  = (const float*)d_in[0];
    const float* efeat  = (const float*)d_in[1];
    const int*   src    = (const int*)d_in[2];
    const int*   dst    = (const int*)d_in[3];
    const float* W_fc   = (const float*)d_in[4];
    const float* attn_l = (const float*)d_in[5];
    const float* attn_r = (const float*)d_in[6];
    const float* bias   = (const float*)d_in[7];
    const float* W_e    = (const float*)d_in[8];
    const float* b_e    = (const float*)d_in[9];
    float* out = (float*)d_out;

    int N = in_sizes[0] / 128;
    int E = in_sizes[2];

    float* d_hf;   cudaGetSymbolAddress((void**)&d_hf,   g_hf);
    float* d_Sagg; cudaGetSymbolAddress((void**)&d_Sagg, g_Sagg);
    int*   d_cnt;  cudaGetSymbolAddress((void**)&d_cnt,  g_cnt);

    cudaMemsetAsync(d_cnt,  0, (size_t)N * sizeof(int));
    cudaMemsetAsync(d_Sagg, 0, (size_t)N * HD * sizeof(float));

    int warps = (E + 3) / 4;
    scatter_kernel<<<(warps * 32 + 255) / 256, 256>>>((const float4*)efeat, dst, E);

    gemm_kernel<<<(N + 127) / 128, 256>>>(nfeat, W_fc, d_hf, N, 0, attn_l, attn_r);
    scan_kernel<<<1, 1024>>>(N, E);
    permute_kernel<<<(E + 255) / 256, 256>>>(src, dst, E);

    node_agg_kernel<<<(N + 7) / 8, 256>>>(out, (const float4*)bias, (const float4*)b_e, N);

    gemm_kernel<<<(N + 127) / 128, 256>>>(d_Sagg, W_e, out, N, 1, nullptr, nullptr);
}

// round 14
// speedup vs baseline: 1.0917x; 1.0917x over previous
#include <cuda_runtime.h>

#define N_MAX 50000
#define E_MAX 800000
#define HD 128
#define NH 8

// ---- scratch (device globals; no allocation allowed) ----
__device__ float g_hf[N_MAX * HD];      // nfeat @ W_fc
__device__ float g_el[N_MAX * NH];
__device__ float g_er[N_MAX * NH];
__device__ float g_denom[N_MAX * NH];
__device__ float g_indeg[N_MAX];
__device__ float g_Sagg[N_MAX * HD];    // segment_sum(efeat)

// vectorized float4 reduction to global memory (sm_90+)
__device__ __forceinline__ void red_add_v4(float* p, float x, float y, float z, float w) {
    asm volatile("red.global.add.v4.f32 [%0], {%1,%2,%3,%4};"
                 :: "l"(p), "f"(x), "f"(y), "f"(z), "f"(w) : "memory");
}
__device__ __forceinline__ void red_add_f32(float* p, float x) {
    asm volatile("red.global.add.f32 [%0], %1;" :: "l"(p), "f"(x) : "memory");
}

// packed f32x2 helpers (FFMA2 — PTX-only path on sm_103a)
__device__ __forceinline__ unsigned long long pack2(float lo, float hi) {
    unsigned long long r;
    asm("mov.b64 %0, {%1, %2};" : "=l"(r) : "r"(__float_as_uint(lo)), "r"(__float_as_uint(hi)));
    return r;
}
__device__ __forceinline__ void fma2(unsigned long long& acc, unsigned long long a, unsigned long long b) {
    asm("fma.rn.f32x2 %0, %1, %2, %0;" : "+l"(acc) : "l"(a), "l"(b));
}
__device__ __forceinline__ void unpack2(unsigned long long v, float& lo, float& hi) {
    unsigned int l, h;
    asm("mov.b64 {%0, %1}, %2;" : "=r"(l), "=r"(h) : "l"(v));
    lo = __uint_as_float(l); hi = __uint_as_float(h);
}

__device__ __forceinline__ float leaky02(float x) { return x > 0.f ? x : 0.2f * x; }

// ---------------- GEMM: 128x128 block tile, 8x8 per thread ----------------
// mode 0: out = A@W, plus el/er head reductions.
// mode 1: fused finalize:
//   out[row] = out[row]*invden + bias + hf[row]*inv1 + (A@W)[row]*invm + b_e*gate
#define KC 32
__global__ __launch_bounds__(256, 2)
void gemm_kernel(const float* __restrict__ A, const float* __restrict__ W,
                 float* __restrict__ out, int nrows, int mode,
                 const float* __restrict__ attn_l, const float* __restrict__ attn_r,
                 const float4* __restrict__ bias4, const float4* __restrict__ be4) {
    __shared__ float Ws[KC][128];
    __shared__ float As[128][KC + 4];
    int t = threadIdx.x;
    int tx = t & 15;
    int ty = t >> 4;
    int rbase = blockIdx.x * 128;

    unsigned long long acc[8][4];
#pragma unroll
    for (int i = 0; i < 8; i++)
#pragma unroll
        for (int j = 0; j < 4; j++) acc[i][j] = 0ull;

    for (int kc = 0; kc < 4; kc++) {
#pragma unroll
        for (int i = 0; i < 4; i++) {
            int lin = i * 256 + t;
            int r = lin >> 5, c4 = lin & 31;
            *((float4*)&Ws[r][c4 * 4]) = ((const float4*)W)[(kc * 32 + r) * 32 + c4];
        }
#pragma unroll
        for (int i = 0; i < 4; i++) {
            int lin = i * 256 + t;
            int r = lin >> 3, k4 = lin & 7;
            int row = rbase + r;
            float4 v = (row < nrows) ? ((const float4*)A)[(size_t)row * 32 + kc * 8 + k4]
                                     : make_float4(0.f, 0.f, 0.f, 0.f);
            *((float4*)&As[r][k4 * 4]) = v;
        }
        __syncthreads();
#pragma unroll
        for (int k = 0; k < KC; k++) {
            unsigned long long w2[4];
#pragma unroll
            for (int j = 0; j < 4; j++)
                w2[j] = *(const unsigned long long*)&Ws[k][tx * 8 + j * 2];
#pragma unroll
            for (int i = 0; i < 8; i++) {
                float a = As[ty * 8 + i][k];
                unsigned long long aa = pack2(a, a);
#pragma unroll
                for (int j = 0; j < 4; j++) fma2(acc[i][j], aa, w2[j]);
            }
        }
        __syncthreads();
    }

    if (mode == 0) {
        float al[8], ar[8];
#pragma unroll
        for (int j = 0; j < 8; j++) { al[j] = attn_l[tx * 8 + j]; ar[j] = attn_r[tx * 8 + j]; }
#pragma unroll
        for (int i = 0; i < 8; i++) {
            int row = rbase + ty * 8 + i;
            float c[8];
#pragma unroll
            for (int j = 0; j < 4; j++) unpack2(acc[i][j], c[2 * j], c[2 * j + 1]);
            if (row < nrows) {
                *(float4*)&out[(size_t)row * 128 + tx * 8]     = make_float4(c[0], c[1], c[2], c[3]);
                *(float4*)&out[(size_t)row * 128 + tx * 8 + 4] = make_float4(c[4], c[5], c[6], c[7]);
            }
            float pl = 0.f, pr = 0.f;
#pragma unroll
            for (int j = 0; j < 8; j++) { pl += c[j] * al[j]; pr += c[j] * ar[j]; }
            pl += __shfl_xor_sync(0xffffffffu, pl, 1);
            pr += __shfl_xor_sync(0xffffffffu, pr, 1);
            if ((tx & 1) == 0 && row < nrows) {
                g_el[row * NH + (tx >> 1)] = pl;
                g_er[row * NH + (tx >> 1)] = pr;
            }
        }
    } else {
        float4 b0 = bias4[tx * 2], b1 = bias4[tx * 2 + 1];
        float4 e0 = be4[tx * 2],   e1 = be4[tx * 2 + 1];
#pragma unroll
        for (int i = 0; i < 8; i++) {
            int row = rbase + ty * 8 + i;
            if (row >= nrows) continue;
            float c[8];
#pragma unroll
            for (int j = 0; j < 4; j++) unpack2(acc[i][j], c[2 * j], c[2 * j + 1]);
            float deg  = g_indeg[row];
            float den  = g_denom[row * NH + (tx >> 1)];
            float invden = den > 0.f ? 1.f / den : 0.f;
            float inv1 = 1.f / (deg + 1.f);
            float invm = 1.f / fmaxf(deg, 1.f);
            float gate = deg > 0.f ? 1.f : 0.f;
            float4 o0 = *(const float4*)&out[(size_t)row * 128 + tx * 8];
            float4 o1 = *(const float4*)&out[(size_t)row * 128 + tx * 8 + 4];
            float4 h0 = *(const float4*)&g_hf[(size_t)row * 128 + tx * 8];
            float4 h1 = *(const float4*)&g_hf[(size_t)row * 128 + tx * 8 + 4];
            o0.x = o0.x * invden + b0.x + h0.x * inv1 + c[0] * invm + e0.x * gate;
            o0.y = o0.y * invden + b0.y + h0.y * inv1 + c[1] * invm + e0.y * gate;
            o0.z = o0.z * invden + b0.z + h0.z * inv1 + c[2] * invm + e0.z * gate;
            o0.w = o0.w * invden + b0.w + h0.w * inv1 + c[3] * invm + e0.w * gate;
            o1.x = o1.x * invden + b1.x + h1.x * inv1 + c[4] * invm + e1.x * gate;
            o1.y = o1.y * invden + b1.y + h1.y * inv1 + c[5] * invm + e1.y * gate;
            o1.z = o1.z * invden + b1.z + h1.z * inv1 + c[6] * invm + e1.z * gate;
            o1.w = o1.w * invden + b1.w + h1.w * inv1 + c[7] * invm + e1.w * gate;
            *(float4*)&out[(size_t)row * 128 + tx * 8]     = o0;
            *(float4*)&out[(size_t)row * 128 + tx * 8 + 4] = o1;
        }
    }
}

// ---------------- fused edge pass (8 edges per warp, all loads batched):
//   Sagg[dst] += efeat[e];  indeg[dst]++
//   ex = exp(leaky(el[src]+er[dst])); denom[dst] += ex; out[dst] += ex*hf[src]
// (softmax max-shift dropped: scores are O(1); division deferred to gemm2 epilogue)
#define EPB 8
__global__ __launch_bounds__(256)
void edge_kernel(const float4* __restrict__ efeat4,
                 const int* __restrict__ src, const int* __restrict__ dst,
                 float* __restrict__ out, int E) {
    int w = (blockIdx.x * blockDim.x + threadIdx.x) >> 5;
    int lane = threadIdx.x & 31;
    int e0 = w * EPB;
    if (e0 >= E) return;
    int ne = E - e0; if (ne > EPB) ne = EPB;

    int sE[EPB], dE[EPB];
#pragma unroll
    for (int q = 0; q < EPB; q++) {
        int e = e0 + (q < ne ? q : ne - 1);
        sE[q] = src[e]; dE[q] = dst[e];
    }
    float4 ef[EPB], hv[EPB];
#pragma unroll
    for (int q = 0; q < EPB; q++)
        ef[q] = __ldcs(&efeat4[(size_t)(e0 + (q < ne ? q : ne - 1)) * 32 + lane]);
#pragma unroll
    for (int q = 0; q < EPB; q++)
        hv[q] = ((const float4*)g_hf)[(size_t)sE[q] * 32 + lane];

    int hh = lane & 7;
    float exv[EPB];
#pragma unroll
    for (int q = 0; q < EPB; q++) {
        float ev = __ldg(&g_el[sE[q] * NH + hh]) + __ldg(&g_er[dE[q] * NH + hh]);
        exv[q] = __expf(leaky02(ev));
    }

    if (lane == 0) {
#pragma unroll
        for (int q = 0; q < EPB; q++)
            if (q < ne) red_add_f32(&g_indeg[dE[q]], 1.0f);
    }
#pragma unroll
    for (int q = 0; q < EPB; q++) {
        if (q < ne) {
            red_add_v4(&g_Sagg[(size_t)dE[q] * 128 + lane * 4],
                       ef[q].x, ef[q].y, ef[q].z, ef[q].w);
            if (lane < 8) red_add_f32(&g_denom[dE[q] * NH + hh], exv[q]);
            float a = __shfl_sync(0xffffffffu, exv[q], lane >> 2);
            red_add_v4(&out[(size_t)dE[q] * 128 + lane * 4],
                       a * hv[q].x, a * hv[q].y, a * hv[q].z, a * hv[q].w);
        }
    }
}

extern "C" void kernel_launch(void* const* d_in, const int* in_sizes, int n_in,
                              void* d_out, int out_size) {
    const float* nfeat  = (const float*)d_in[0];
    const float* efeat  = (const float*)d_in[1];
    const int*   src    = (const int*)d_in[2];
    const int*   dst    = (const int*)d_in[3];
    const float* W_fc   = (const float*)d_in[4];
    const float* attn_l = (const float*)d_in[5];
    const float* attn_r = (const float*)d_in[6];
    const float* bias   = (const float*)d_in[7];
    const float* W_e    = (const float*)d_in[8];
    const float* b_e    = (const float*)d_in[9];
    float* out = (float*)d_out;

    int N = in_sizes[0] / 128;
    int E = in_sizes[2];

    float* d_hf;    cudaGetSymbolAddress((void**)&d_hf,    g_hf);
    float* d_Sagg;  cudaGetSymbolAddress((void**)&d_Sagg,  g_Sagg);
    float* d_denom; cudaGetSymbolAddress((void**)&d_denom, g_denom);
    float* d_indeg; cudaGetSymbolAddress((void**)&d_indeg, g_indeg);

    cudaMemsetAsync(out,     0, (size_t)N * HD * sizeof(float));
    cudaMemsetAsync(d_Sagg,  0, (size_t)N * HD * sizeof(float));
    cudaMemsetAsync(d_denom, 0, (size_t)N * NH * sizeof(float));
    cudaMemsetAsync(d_indeg, 0, (size_t)N * sizeof(float));

    gemm_kernel<<<(N + 127) / 128, 256>>>(nfeat, W_fc, d_hf, N, 0, attn_l, attn_r,
                                          nullptr, nullptr);

    int warps = (E + EPB - 1) / EPB;
    edge_kernel<<<(warps * 32 + 255) / 256, 256>>>((const float4*)efeat, src, dst, out, E);

    gemm_kernel<<<(N + 127) / 128, 256>>>(d_Sagg, W_e, out, N, 1, nullptr, nullptr,
                                          (const float4*)bias, (const float4*)b_e);
}